// round 15
// baseline (speedup 1.0000x reference)
#include <cuda_runtime.h>
#include <cuda_bf16.h>

// GraphSAGE, 2-layer, mean aggregation.
//   h1  = relu(mean_agg(x) @ W1_l + b1 + x @ W1_r)
//   out = mean_agg(h1) @ W2_l + b2 + h1 @ W2_r
// Structure (6 launches):
//   count -> scan(single-pass, decoupled lookback) -> fill(atomic-free)
//         -> agg1(fp32 gather) -> h1(f32x2 GEMM) -> out
// Transforms:
//   - layer-2 is 64->1: aggregate SCALARS; h1 never materialized.
//   - CSR by counting sort; count's atomicAdd return value IS each edge's
//     rank within its dst row -> fill needs no atomics at all.
//   - single-kernel scan: blocks publish chunk totals with a flag bit packed
//     in the same 32-bit word; warp 0 lookback-sums predecessors. 98 blocks
//     all co-resident on 148 SMs -> no deadlock. fill resets the flags.
//   - dtype-detect (int32 vs int64 edge_index) inlined per-warp.

#define MAXN 100000
#define MAXE 1600000
#define F 64
#define SCAN_CHUNK 1024
#define MAX_BLOCKS_SCAN 128
#define PUB_FLAG (1 << 30)

typedef unsigned long long ull;

// ---- device scratch (static; allocation is forbidden) ----
__device__ int g_deg[MAXN];            // zero at load; re-zeroed by agg1 each call
__device__ int g_rowstart[MAXN + 1];
__device__ int g_rank[MAXE];
__device__ int g_csr[MAXE];
__device__ volatile int g_pub[MAX_BLOCKS_SCAN];  // zero at load; reset by fill
__device__ __align__(16) float g_agg1[(size_t)MAXN * F];
__device__ float g_s[MAXN];
__device__ float g_r[MAXN];

// ---- packed f32x2 helpers -------------------------------------------------
__device__ __forceinline__ ull pk2(float v) {
    ull r; asm("mov.b64 %0, {%1, %1};" : "=l"(r) : "f"(v)); return r;
}
__device__ __forceinline__ ull fma2(ull a, ull b, ull c) {
    ull d; asm("fma.rn.f32x2 %0, %1, %2, %3;" : "=l"(d) : "l"(a), "l"(b), "l"(c));
    return d;
}
__device__ __forceinline__ void upk2(ull v, float& lo, float& hi) {
    asm("mov.b64 {%0, %1}, %2;" : "=f"(lo), "=f"(hi) : "l"(v));
}

// Per-warp dtype detection: viewed as int32, an int64 buffer (ids < 2^31)
// has all odd words zero; an int32 buffer has random node ids there.
__device__ __forceinline__ int warp_is64(const int* __restrict__ ei) {
    int lane = threadIdx.x & 31;
    int nz = ei[2 * lane + 1];
    #pragma unroll
    for (int d = 16; d; d >>= 1) nz |= __shfl_xor_sync(0xffffffffu, nz, d);
    return nz == 0;
}

// ---------------------------------------------------------------------------
// 4 edges per thread. dst[j] lives at element e+j. The atomicAdd return is
// this edge's rank within its dst row -> stored for the atomic-free fill.
__global__ void count_kernel(const int* __restrict__ ei, int e, int n) {
    int is64 = warp_is64(ei);
    int idx0 = (blockIdx.x * blockDim.x + threadIdx.x) * 4;
    if (idx0 >= e) return;
    int cnt = e - idx0; if (cnt > 4) cnt = 4;
    int d[4];
    if (cnt == 4) {
        if (is64) {
            if (((e + idx0) & 1) == 0) {
                int4 a = *(const int4*)&ei[2 * (e + idx0)];
                int4 b = *(const int4*)&ei[2 * (e + idx0) + 4];
                d[0] = a.x; d[1] = a.z; d[2] = b.x; d[3] = b.z;
            } else {
                #pragma unroll
                for (int i = 0; i < 4; i++) d[i] = ei[2 * (e + idx0 + i)];
            }
        } else {
            if (((e + idx0) & 3) == 0) {
                int4 a = *(const int4*)&ei[e + idx0];
                d[0] = a.x; d[1] = a.y; d[2] = a.z; d[3] = a.w;
            } else {
                #pragma unroll
                for (int i = 0; i < 4; i++) d[i] = ei[e + idx0 + i];
            }
        }
    } else {
        for (int i = 0; i < cnt; i++)
            d[i] = is64 ? ei[2 * (e + idx0 + i)] : ei[e + idx0 + i];
    }
    int r[4] = {0, 0, 0, 0};
    #pragma unroll
    for (int i = 0; i < 4; i++)
        if (i < cnt && (unsigned)d[i] < (unsigned)n)
            r[i] = atomicAdd(&g_deg[d[i]], 1);
    if (cnt == 4 && ((idx0 & 3) == 0)) {
        *(int4*)&g_rank[idx0] = make_int4(r[0], r[1], r[2], r[3]);
    } else {
        for (int i = 0; i < cnt; i++) g_rank[idx0 + i] = r[i];
    }
}

// Single-pass scan with decoupled lookback. 98 blocks, chunk = 1024
// (256 threads x 4). Publishes (total | PUB_FLAG) into g_pub[b]; warp 0
// spin-reads all predecessors 32 at a time. All blocks co-resident.
__global__ void scan_kernel(int n, int nb) {
    __shared__ int wsum[8];
    __shared__ int s_boff, s_btot;
    const int tid = threadIdx.x, lane = tid & 31, wid = tid >> 5;
    const int bid = blockIdx.x;
    int base = bid * SCAN_CHUNK;
    int i0 = base + tid * 4;
    int v0 = (i0 + 0 < n) ? g_deg[i0 + 0] : 0;
    int v1 = (i0 + 1 < n) ? g_deg[i0 + 1] : 0;
    int v2 = (i0 + 2 < n) ? g_deg[i0 + 2] : 0;
    int v3 = (i0 + 3 < n) ? g_deg[i0 + 3] : 0;
    int tsum = v0 + v1 + v2 + v3;

    int xs = tsum;
    #pragma unroll
    for (int d = 1; d < 32; d <<= 1) {
        int t = __shfl_up_sync(0xffffffffu, xs, d);
        if (lane >= d) xs += t;
    }
    if (lane == 31) wsum[wid] = xs;
    __syncthreads();
    if (wid == 0) {
        // inclusive scan of the 8 per-warp sums
        int w = (lane < 8) ? wsum[lane] : 0;
        #pragma unroll
        for (int d = 1; d < 8; d <<= 1) {
            int t = __shfl_up_sync(0xffffffffu, w, d);
            if (lane >= d) w += t;
        }
        if (lane < 8) wsum[lane] = w;
        int btot = __shfl_sync(0xffffffffu, w, 7);
        // publish ASAP (flag packed in the same word -> no fence needed)
        if (lane == 0) g_pub[bid] = btot | PUB_FLAG;
        // lookback: sum totals of blocks 0..bid-1, 32 at a time
        int myoff = 0;
        for (int b = 0; b < bid; b += 32) {
            int i = b + lane;
            int v = 0;
            if (i < bid) {
                do { v = g_pub[i]; } while (!(v & PUB_FLAG));
                v &= ~PUB_FLAG;
            }
            #pragma unroll
            for (int d = 16; d; d >>= 1) v += __shfl_xor_sync(0xffffffffu, v, d);
            myoff += v;
        }
        if (lane == 0) { s_boff = myoff; s_btot = btot; }
    }
    __syncthreads();
    int warp_off = (wid == 0) ? 0 : wsum[wid - 1];
    int excl = s_boff + warp_off + xs - tsum;

    int e0 = excl;
    int e1 = e0 + v0;
    int e2 = e1 + v1;
    int e3 = e2 + v2;
    if (i0 + 0 < n) g_rowstart[i0 + 0] = e0;
    if (i0 + 1 < n) g_rowstart[i0 + 1] = e1;
    if (i0 + 2 < n) g_rowstart[i0 + 2] = e2;
    if (i0 + 3 < n) g_rowstart[i0 + 3] = e3;
    if (bid == nb - 1 && tid == 0) g_rowstart[n] = s_boff + s_btot;
}

// Atomic-free fill: pos = rowstart[dst] + rank (rank saved by count).
// Also resets the scan publish flags for the next graph replay.
__global__ void fill_kernel(const int* __restrict__ ei, int e, int n) {
    if (blockIdx.x == 0 && threadIdx.x < MAX_BLOCKS_SCAN)
        g_pub[threadIdx.x] = 0;
    int is64 = warp_is64(ei);
    int idx0 = (blockIdx.x * blockDim.x + threadIdx.x) * 4;
    if (idx0 >= e) return;
    int cnt = e - idx0; if (cnt > 4) cnt = 4;
    int s[4], d[4], r[4];
    if (cnt == 4 && ((idx0 & 3) == 0)) {
        int4 ra = *(const int4*)&g_rank[idx0];
        r[0] = ra.x; r[1] = ra.y; r[2] = ra.z; r[3] = ra.w;
    } else {
        for (int i = 0; i < cnt; i++) r[i] = g_rank[idx0 + i];
    }
    if (cnt == 4) {
        if (is64) {
            int4 sa = *(const int4*)&ei[2 * idx0];
            int4 sb = *(const int4*)&ei[2 * idx0 + 4];
            s[0] = sa.x; s[1] = sa.z; s[2] = sb.x; s[3] = sb.z;
            if (((e + idx0) & 1) == 0) {
                int4 da = *(const int4*)&ei[2 * (e + idx0)];
                int4 db = *(const int4*)&ei[2 * (e + idx0) + 4];
                d[0] = da.x; d[1] = da.z; d[2] = db.x; d[3] = db.z;
            } else {
                #pragma unroll
                for (int i = 0; i < 4; i++) d[i] = ei[2 * (e + idx0 + i)];
            }
        } else {
            int4 sa = *(const int4*)&ei[idx0];
            s[0] = sa.x; s[1] = sa.y; s[2] = sa.z; s[3] = sa.w;
            if (((e + idx0) & 3) == 0) {
                int4 da = *(const int4*)&ei[e + idx0];
                d[0] = da.x; d[1] = da.y; d[2] = da.z; d[3] = da.w;
            } else {
                #pragma unroll
                for (int i = 0; i < 4; i++) d[i] = ei[e + idx0 + i];
            }
        }
    } else {
        for (int i = 0; i < cnt; i++) {
            s[i] = is64 ? ei[2 * (idx0 + i)] : ei[idx0 + i];
            d[i] = is64 ? ei[2 * (e + idx0 + i)] : ei[e + idx0 + i];
        }
    }
    #pragma unroll
    for (int i = 0; i < 4; i++) {
        if (i < cnt && (unsigned)d[i] < (unsigned)n && (unsigned)s[i] < (unsigned)n) {
            g_csr[g_rowstart[d[i]] + r[i]] = s[i];
        }
    }
}

// Half-warp (16 lanes, one float4 each) per node: gather-sum x rows over the
// node's in-edges (unroll-by-2), write mean. Re-zeroes g_deg for next call.
__global__ void agg1_kernel(const float* __restrict__ x, int n) {
    int gt = blockIdx.x * blockDim.x + threadIdx.x;
    int node = gt >> 4;
    int q = gt & 15;
    if (node >= n) return;
    if (q == 0) g_deg[node] = 0;
    int beg = g_rowstart[node];
    int end = g_rowstart[node + 1];
    const float4* __restrict__ x4 = (const float4*)x;
    float4 acc = make_float4(0.f, 0.f, 0.f, 0.f);
    float4 acc2 = make_float4(0.f, 0.f, 0.f, 0.f);
    int j = beg;
    for (; j + 1 < end; j += 2) {
        int s0 = g_csr[j];
        int s1 = g_csr[j + 1];
        float4 v0 = x4[(size_t)s0 * 16 + q];
        float4 v1 = x4[(size_t)s1 * 16 + q];
        acc.x += v0.x; acc.y += v0.y; acc.z += v0.z; acc.w += v0.w;
        acc2.x += v1.x; acc2.y += v1.y; acc2.z += v1.z; acc2.w += v1.w;
    }
    if (j < end) {
        int s0 = g_csr[j];
        float4 v0 = x4[(size_t)s0 * 16 + q];
        acc.x += v0.x; acc.y += v0.y; acc.z += v0.z; acc.w += v0.w;
    }
    acc.x += acc2.x; acc.y += acc2.y; acc.z += acc2.z; acc.w += acc2.w;
    int deg = end - beg;
    float inv = 1.0f / (float)(deg > 0 ? deg : 1);
    acc.x *= inv; acc.y *= inv; acc.z *= inv; acc.w *= inv;
    ((float4*)g_agg1)[(size_t)node * 16 + q] = acc;
}

// 2 nodes per thread; packed fma.rn.f32x2 accumulators. s/r computed
// in-register; h1 never stored.
__global__ __launch_bounds__(128) void h1_kernel(
    const float* __restrict__ x,
    const float* __restrict__ W1l, const float* __restrict__ b1,
    const float* __restrict__ W1r,
    const float* __restrict__ W2l, const float* __restrict__ W2r,
    int n) {
    __shared__ __align__(16) float sWl[F * F];
    __shared__ __align__(16) float sWr[F * F];
    __shared__ __align__(8) float sb1[F], sW2l[F], sW2r[F];
    for (int idx = threadIdx.x; idx < F * F; idx += blockDim.x) {
        sWl[idx] = W1l[idx];
        sWr[idx] = W1r[idx];
    }
    if (threadIdx.x < F) {
        sb1[threadIdx.x]  = b1[threadIdx.x];
        sW2l[threadIdx.x] = W2l[threadIdx.x];
        sW2r[threadIdx.x] = W2r[threadIdx.x];
    }
    __syncthreads();

    int t = blockIdx.x * blockDim.x + threadIdx.x;
    int i0 = t * 2;
    if (i0 >= n) return;
    bool has1 = (i0 + 1 < n);
    int i1 = has1 ? (i0 + 1) : i0;

    const ull* sWl64 = (const ull*)sWl;
    const ull* sWr64 = (const ull*)sWr;

    ull acc0[32], acc1[32];
    #pragma unroll
    for (int j = 0; j < 32; j++) {
        ull b = ((const ull*)sb1)[j];
        acc0[j] = b;
        acc1[j] = b;
    }

    const float4* __restrict__ ag0 = ((const float4*)g_agg1) + (size_t)i0 * 16;
    const float4* __restrict__ ag1 = ((const float4*)g_agg1) + (size_t)i1 * 16;
    const float4* __restrict__ xx0 = ((const float4*)x) + (size_t)i0 * 16;
    const float4* __restrict__ xx1 = ((const float4*)x) + (size_t)i1 * 16;

    #pragma unroll 1
    for (int kc = 0; kc < 16; kc++) {
        float4 a0 = ag0[kc], b0 = xx0[kc];
        float4 a1 = ag1[kc], b1v = xx1[kc];
        float av0[4] = {a0.x, a0.y, a0.z, a0.w};
        float xv0[4] = {b0.x, b0.y, b0.z, b0.w};
        float av1[4] = {a1.x, a1.y, a1.z, a1.w};
        float xv1[4] = {b1v.x, b1v.y, b1v.z, b1v.w};
        #pragma unroll
        for (int kk = 0; kk < 4; kk++) {
            int k = kc * 4 + kk;
            ull apk0 = pk2(av0[kk]), xpk0 = pk2(xv0[kk]);
            ull apk1 = pk2(av1[kk]), xpk1 = pk2(xv1[kk]);
            const ull* wl = sWl64 + k * 32;
            const ull* wr = sWr64 + k * 32;
            #pragma unroll
            for (int j = 0; j < 32; j++) {
                ull w1 = wl[j];
                ull w2 = wr[j];
                acc0[j] = fma2(w1, apk0, acc0[j]);
                acc0[j] = fma2(w2, xpk0, acc0[j]);
                acc1[j] = fma2(w1, apk1, acc1[j]);
                acc1[j] = fma2(w2, xpk1, acc1[j]);
            }
        }
    }

    float s0 = 0.f, r0 = 0.f, s1 = 0.f, r1 = 0.f;
    #pragma unroll
    for (int j = 0; j < 32; j++) {
        float lo, hi;
        upk2(acc0[j], lo, hi);
        float h0 = fmaxf(lo, 0.f), h1v = fmaxf(hi, 0.f);
        s0 += h0 * sW2l[2 * j] + h1v * sW2l[2 * j + 1];
        r0 += h0 * sW2r[2 * j] + h1v * sW2r[2 * j + 1];
        upk2(acc1[j], lo, hi);
        float g0 = fmaxf(lo, 0.f), g1 = fmaxf(hi, 0.f);
        s1 += g0 * sW2l[2 * j] + g1 * sW2l[2 * j + 1];
        r1 += g0 * sW2r[2 * j] + g1 * sW2r[2 * j + 1];
    }
    g_s[i0] = s0;
    g_r[i0] = r0;
    if (has1) { g_s[i1] = s1; g_r[i1] = r1; }
}

// One thread per node: out[i] = mean_j s[j] + b2 + r[i]  (unroll-by-2)
__global__ void out_kernel(const float* __restrict__ b2,
                           float* __restrict__ out, int n) {
    int i = blockIdx.x * blockDim.x + threadIdx.x;
    if (i >= n) return;
    int beg = g_rowstart[i];
    int end = g_rowstart[i + 1];
    float sum = 0.f, sum2 = 0.f;
    int j = beg;
    for (; j + 1 < end; j += 2) {
        sum  += g_s[g_csr[j]];
        sum2 += g_s[g_csr[j + 1]];
    }
    if (j < end) sum += g_s[g_csr[j]];
    sum += sum2;
    int deg = end - beg;
    float inv = 1.0f / (float)(deg > 0 ? deg : 1);
    out[i] = sum * inv + b2[0] + g_r[i];
}

// ---------------------------------------------------------------------------
extern "C" void kernel_launch(void* const* d_in, const int* in_sizes, int n_in,
                              void* d_out, int out_size) {
    const float* x   = (const float*)d_in[0];
    const int*   ei  = (const int*)d_in[1];   // int32 OR int64 (warp-detected)
    const float* W1l = (const float*)d_in[2];
    const float* b1  = (const float*)d_in[3];
    const float* W1r = (const float*)d_in[4];
    const float* W2l = (const float*)d_in[5];
    const float* b2  = (const float*)d_in[6];
    const float* W2r = (const float*)d_in[7];
    float* out = (float*)d_out;

    int n = in_sizes[0] / F;      // 100000
    int e = in_sizes[1] / 2;      // 1600000
    int nb = (n + SCAN_CHUNK - 1) / SCAN_CHUNK;   // 98
    int et = (e + 3) / 4;         // edge threads (4 edges each)

    count_kernel<<<(et + 255) / 256, 256>>>(ei, e, n);
    scan_kernel<<<nb, 256>>>(n, nb);
    fill_kernel<<<(et + 255) / 256, 256>>>(ei, e, n);
    agg1_kernel<<<(n * 16 + 255) / 256, 256>>>(x, n);
    h1_kernel<<<((n + 1) / 2 + 127) / 128, 128>>>(x, W1l, b1, W1r, W2l, W2r, n);
    out_kernel<<<(n + 255) / 256, 256>>>(b2, out, n);
}

// round 17
// speedup vs baseline: 1.4458x; 1.4458x over previous
#include <cuda_runtime.h>
#include <cuda_bf16.h>

// GraphSAGE, 2-layer, mean aggregation.
//   h1  = relu(mean_agg(x) @ W1_l + b1 + x @ W1_r)
//   out = mean_agg(h1) @ W2_l + b2 + h1 @ W2_r
// Structure (6 launches):
//   count(RED atomics) -> scan(single-pass lookback) -> fill(cursor atomics)
//         -> agg1(fp32 gather) -> h1(f32x2 GEMM) -> out
// Lessons encoded:
//   - count must DISCARD the atomicAdd return (REDG, fire-and-forget);
//     consuming it (R15 rank scheme) turns it into latency-exposed ATOMG
//     with a dependent store: +60us.
//   - agg1 is latency/issue bound at ~48us (R15 ncu), not BW bound; fp16
//     payload shrink doesn't help (R8/R11).
//   - layer-2 is 64->1: aggregate SCALARS; h1 never materialized.
//   - dtype-detect (int32 vs int64 edge_index) inlined per-warp.

#define MAXN 100000
#define MAXE 1600000
#define F 64
#define SCAN_CHUNK 1024
#define MAX_BLOCKS_SCAN 128
#define PUB_FLAG (1 << 30)

typedef unsigned long long ull;

// ---- device scratch (static; allocation is forbidden) ----
__device__ int g_deg[MAXN];            // zero at load; re-zeroed by agg1 each call
__device__ int g_rowstart[MAXN + 1];
__device__ int g_cursor[MAXN];
__device__ int g_csr[MAXE];
__device__ volatile int g_pub[MAX_BLOCKS_SCAN];  // zero at load; reset by fill
__device__ __align__(16) float g_agg1[(size_t)MAXN * F];
__device__ float g_s[MAXN];
__device__ float g_r[MAXN];

// ---- packed f32x2 helpers -------------------------------------------------
__device__ __forceinline__ ull pk2(float v) {
    ull r; asm("mov.b64 %0, {%1, %1};" : "=l"(r) : "f"(v)); return r;
}
__device__ __forceinline__ ull fma2(ull a, ull b, ull c) {
    ull d; asm("fma.rn.f32x2 %0, %1, %2, %3;" : "=l"(d) : "l"(a), "l"(b), "l"(c));
    return d;
}
__device__ __forceinline__ void upk2(ull v, float& lo, float& hi) {
    asm("mov.b64 {%0, %1}, %2;" : "=f"(lo), "=f"(hi) : "l"(v));
}

// Per-warp dtype detection: viewed as int32, an int64 buffer (ids < 2^31)
// has all odd words zero; an int32 buffer has random node ids there.
__device__ __forceinline__ int warp_is64(const int* __restrict__ ei) {
    int lane = threadIdx.x & 31;
    int nz = ei[2 * lane + 1];
    #pragma unroll
    for (int d = 16; d; d >>= 1) nz |= __shfl_xor_sync(0xffffffffu, nz, d);
    return nz == 0;
}

// ---------------------------------------------------------------------------
// 4 edges per thread; atomicAdd return DISCARDED (REDG fast path).
__global__ void count_kernel(const int* __restrict__ ei, int e, int n) {
    int is64 = warp_is64(ei);
    int idx0 = (blockIdx.x * blockDim.x + threadIdx.x) * 4;
    if (idx0 >= e) return;
    int cnt = e - idx0; if (cnt > 4) cnt = 4;
    int d[4];
    if (cnt == 4) {
        if (is64) {
            if (((e + idx0) & 1) == 0) {
                int4 a = *(const int4*)&ei[2 * (e + idx0)];
                int4 b = *(const int4*)&ei[2 * (e + idx0) + 4];
                d[0] = a.x; d[1] = a.z; d[2] = b.x; d[3] = b.z;
            } else {
                #pragma unroll
                for (int i = 0; i < 4; i++) d[i] = ei[2 * (e + idx0 + i)];
            }
        } else {
            if (((e + idx0) & 3) == 0) {
                int4 a = *(const int4*)&ei[e + idx0];
                d[0] = a.x; d[1] = a.y; d[2] = a.z; d[3] = a.w;
            } else {
                #pragma unroll
                for (int i = 0; i < 4; i++) d[i] = ei[e + idx0 + i];
            }
        }
    } else {
        for (int i = 0; i < cnt; i++)
            d[i] = is64 ? ei[2 * (e + idx0 + i)] : ei[e + idx0 + i];
    }
    #pragma unroll
    for (int i = 0; i < 4; i++)
        if (i < cnt && (unsigned)d[i] < (unsigned)n) atomicAdd(&g_deg[d[i]], 1);
}

// Single-pass scan with decoupled lookback. 98 blocks, chunk = 1024
// (256 threads x 4). Publishes (total | PUB_FLAG) into g_pub[b]; warp 0
// spin-reads all predecessors 32 at a time. All blocks co-resident.
// Writes g_rowstart AND g_cursor (for fill's cursor atomics).
__global__ void scan_kernel(int n, int nb) {
    __shared__ int wsum[8];
    __shared__ int s_boff, s_btot;
    const int tid = threadIdx.x, lane = tid & 31, wid = tid >> 5;
    const int bid = blockIdx.x;
    int base = bid * SCAN_CHUNK;
    int i0 = base + tid * 4;
    int v0 = (i0 + 0 < n) ? g_deg[i0 + 0] : 0;
    int v1 = (i0 + 1 < n) ? g_deg[i0 + 1] : 0;
    int v2 = (i0 + 2 < n) ? g_deg[i0 + 2] : 0;
    int v3 = (i0 + 3 < n) ? g_deg[i0 + 3] : 0;
    int tsum = v0 + v1 + v2 + v3;

    int xs = tsum;
    #pragma unroll
    for (int d = 1; d < 32; d <<= 1) {
        int t = __shfl_up_sync(0xffffffffu, xs, d);
        if (lane >= d) xs += t;
    }
    if (lane == 31) wsum[wid] = xs;
    __syncthreads();
    if (wid == 0) {
        int w = (lane < 8) ? wsum[lane] : 0;
        #pragma unroll
        for (int d = 1; d < 8; d <<= 1) {
            int t = __shfl_up_sync(0xffffffffu, w, d);
            if (lane >= d) w += t;
        }
        if (lane < 8) wsum[lane] = w;
        int btot = __shfl_sync(0xffffffffu, w, 7);
        if (lane == 0) g_pub[bid] = btot | PUB_FLAG;   // publish ASAP
        int myoff = 0;
        for (int b = 0; b < bid; b += 32) {
            int i = b + lane;
            int v = 0;
            if (i < bid) {
                do { v = g_pub[i]; } while (!(v & PUB_FLAG));
                v &= ~PUB_FLAG;
            }
            #pragma unroll
            for (int d = 16; d; d >>= 1) v += __shfl_xor_sync(0xffffffffu, v, d);
            myoff += v;
        }
        if (lane == 0) { s_boff = myoff; s_btot = btot; }
    }
    __syncthreads();
    int warp_off = (wid == 0) ? 0 : wsum[wid - 1];
    int excl = s_boff + warp_off + xs - tsum;

    int e0 = excl;
    int e1 = e0 + v0;
    int e2 = e1 + v1;
    int e3 = e2 + v2;
    if (i0 + 0 < n) { g_rowstart[i0 + 0] = e0; g_cursor[i0 + 0] = e0; }
    if (i0 + 1 < n) { g_rowstart[i0 + 1] = e1; g_cursor[i0 + 1] = e1; }
    if (i0 + 2 < n) { g_rowstart[i0 + 2] = e2; g_cursor[i0 + 2] = e2; }
    if (i0 + 3 < n) { g_rowstart[i0 + 3] = e3; g_cursor[i0 + 3] = e3; }
    if (bid == nb - 1 && tid == 0) g_rowstart[n] = s_boff + s_btot;
}

// Cursor-atomic fill (proven 25-27us). Also resets scan publish flags.
__global__ void fill_kernel(const int* __restrict__ ei, int e, int n) {
    if (blockIdx.x == 0 && threadIdx.x < MAX_BLOCKS_SCAN)
        g_pub[threadIdx.x] = 0;
    int is64 = warp_is64(ei);
    int idx0 = (blockIdx.x * blockDim.x + threadIdx.x) * 4;
    if (idx0 >= e) return;
    int cnt = e - idx0; if (cnt > 4) cnt = 4;
    int s[4], d[4];
    if (cnt == 4) {
        if (is64) {
            int4 sa = *(const int4*)&ei[2 * idx0];
            int4 sb = *(const int4*)&ei[2 * idx0 + 4];
            s[0] = sa.x; s[1] = sa.z; s[2] = sb.x; s[3] = sb.z;
            if (((e + idx0) & 1) == 0) {
                int4 da = *(const int4*)&ei[2 * (e + idx0)];
                int4 db = *(const int4*)&ei[2 * (e + idx0) + 4];
                d[0] = da.x; d[1] = da.z; d[2] = db.x; d[3] = db.z;
            } else {
                #pragma unroll
                for (int i = 0; i < 4; i++) d[i] = ei[2 * (e + idx0 + i)];
            }
        } else {
            int4 sa = *(const int4*)&ei[idx0];
            s[0] = sa.x; s[1] = sa.y; s[2] = sa.z; s[3] = sa.w;
            if (((e + idx0) & 3) == 0) {
                int4 da = *(const int4*)&ei[e + idx0];
                d[0] = da.x; d[1] = da.y; d[2] = da.z; d[3] = da.w;
            } else {
                #pragma unroll
                for (int i = 0; i < 4; i++) d[i] = ei[e + idx0 + i];
            }
        }
    } else {
        for (int i = 0; i < cnt; i++) {
            s[i] = is64 ? ei[2 * (idx0 + i)] : ei[idx0 + i];
            d[i] = is64 ? ei[2 * (e + idx0 + i)] : ei[e + idx0 + i];
        }
    }
    #pragma unroll
    for (int i = 0; i < 4; i++) {
        if (i < cnt && (unsigned)d[i] < (unsigned)n && (unsigned)s[i] < (unsigned)n) {
            int pos = atomicAdd(&g_cursor[d[i]], 1);
            g_csr[pos] = s[i];
        }
    }
}

// Half-warp (16 lanes, one float4 each) per node: gather-sum x rows over the
// node's in-edges (unroll-by-2), write mean. Re-zeroes g_deg for next call.
__global__ void agg1_kernel(const float* __restrict__ x, int n) {
    int gt = blockIdx.x * blockDim.x + threadIdx.x;
    int node = gt >> 4;
    int q = gt & 15;
    if (node >= n) return;
    if (q == 0) g_deg[node] = 0;
    int beg = g_rowstart[node];
    int end = g_rowstart[node + 1];
    const float4* __restrict__ x4 = (const float4*)x;
    float4 acc = make_float4(0.f, 0.f, 0.f, 0.f);
    float4 acc2 = make_float4(0.f, 0.f, 0.f, 0.f);
    int j = beg;
    for (; j + 1 < end; j += 2) {
        int s0 = g_csr[j];
        int s1 = g_csr[j + 1];
        float4 v0 = x4[(size_t)s0 * 16 + q];
        float4 v1 = x4[(size_t)s1 * 16 + q];
        acc.x += v0.x; acc.y += v0.y; acc.z += v0.z; acc.w += v0.w;
        acc2.x += v1.x; acc2.y += v1.y; acc2.z += v1.z; acc2.w += v1.w;
    }
    if (j < end) {
        int s0 = g_csr[j];
        float4 v0 = x4[(size_t)s0 * 16 + q];
        acc.x += v0.x; acc.y += v0.y; acc.z += v0.z; acc.w += v0.w;
    }
    acc.x += acc2.x; acc.y += acc2.y; acc.z += acc2.z; acc.w += acc2.w;
    int deg = end - beg;
    float inv = 1.0f / (float)(deg > 0 ? deg : 1);
    acc.x *= inv; acc.y *= inv; acc.z *= inv; acc.w *= inv;
    ((float4*)g_agg1)[(size_t)node * 16 + q] = acc;
}

// 2 nodes per thread; packed fma.rn.f32x2 accumulators. s/r computed
// in-register; h1 never stored.
__global__ __launch_bounds__(128) void h1_kernel(
    const float* __restrict__ x,
    const float* __restrict__ W1l, const float* __restrict__ b1,
    const float* __restrict__ W1r,
    const float* __restrict__ W2l, const float* __restrict__ W2r,
    int n) {
    __shared__ __align__(16) float sWl[F * F];
    __shared__ __align__(16) float sWr[F * F];
    __shared__ __align__(8) float sb1[F], sW2l[F], sW2r[F];
    for (int idx = threadIdx.x; idx < F * F; idx += blockDim.x) {
        sWl[idx] = W1l[idx];
        sWr[idx] = W1r[idx];
    }
    if (threadIdx.x < F) {
        sb1[threadIdx.x]  = b1[threadIdx.x];
        sW2l[threadIdx.x] = W2l[threadIdx.x];
        sW2r[threadIdx.x] = W2r[threadIdx.x];
    }
    __syncthreads();

    int t = blockIdx.x * blockDim.x + threadIdx.x;
    int i0 = t * 2;
    if (i0 >= n) return;
    bool has1 = (i0 + 1 < n);
    int i1 = has1 ? (i0 + 1) : i0;

    const ull* sWl64 = (const ull*)sWl;
    const ull* sWr64 = (const ull*)sWr;

    ull acc0[32], acc1[32];
    #pragma unroll
    for (int j = 0; j < 32; j++) {
        ull b = ((const ull*)sb1)[j];
        acc0[j] = b;
        acc1[j] = b;
    }

    const float4* __restrict__ ag0 = ((const float4*)g_agg1) + (size_t)i0 * 16;
    const float4* __restrict__ ag1 = ((const float4*)g_agg1) + (size_t)i1 * 16;
    const float4* __restrict__ xx0 = ((const float4*)x) + (size_t)i0 * 16;
    const float4* __restrict__ xx1 = ((const float4*)x) + (size_t)i1 * 16;

    #pragma unroll 1
    for (int kc = 0; kc < 16; kc++) {
        float4 a0 = ag0[kc], b0 = xx0[kc];
        float4 a1 = ag1[kc], b1v = xx1[kc];
        float av0[4] = {a0.x, a0.y, a0.z, a0.w};
        float xv0[4] = {b0.x, b0.y, b0.z, b0.w};
        float av1[4] = {a1.x, a1.y, a1.z, a1.w};
        float xv1[4] = {b1v.x, b1v.y, b1v.z, b1v.w};
        #pragma unroll
        for (int kk = 0; kk < 4; kk++) {
            int k = kc * 4 + kk;
            ull apk0 = pk2(av0[kk]), xpk0 = pk2(xv0[kk]);
            ull apk1 = pk2(av1[kk]), xpk1 = pk2(xv1[kk]);
            const ull* wl = sWl64 + k * 32;
            const ull* wr = sWr64 + k * 32;
            #pragma unroll
            for (int j = 0; j < 32; j++) {
                ull w1 = wl[j];
                ull w2 = wr[j];
                acc0[j] = fma2(w1, apk0, acc0[j]);
                acc0[j] = fma2(w2, xpk0, acc0[j]);
                acc1[j] = fma2(w1, apk1, acc1[j]);
                acc1[j] = fma2(w2, xpk1, acc1[j]);
            }
        }
    }

    float s0 = 0.f, r0 = 0.f, s1 = 0.f, r1 = 0.f;
    #pragma unroll
    for (int j = 0; j < 32; j++) {
        float lo, hi;
        upk2(acc0[j], lo, hi);
        float h0 = fmaxf(lo, 0.f), h1v = fmaxf(hi, 0.f);
        s0 += h0 * sW2l[2 * j] + h1v * sW2l[2 * j + 1];
        r0 += h0 * sW2r[2 * j] + h1v * sW2r[2 * j + 1];
        upk2(acc1[j], lo, hi);
        float g0 = fmaxf(lo, 0.f), g1 = fmaxf(hi, 0.f);
        s1 += g0 * sW2l[2 * j] + g1 * sW2l[2 * j + 1];
        r1 += g0 * sW2r[2 * j] + g1 * sW2r[2 * j + 1];
    }
    g_s[i0] = s0;
    g_r[i0] = r0;
    if (has1) { g_s[i1] = s1; g_r[i1] = r1; }
}

// One thread per node: out[i] = mean_j s[j] + b2 + r[i]  (unroll-by-2)
__global__ void out_kernel(const float* __restrict__ b2,
                           float* __restrict__ out, int n) {
    int i = blockIdx.x * blockDim.x + threadIdx.x;
    if (i >= n) return;
    int beg = g_rowstart[i];
    int end = g_rowstart[i + 1];
    float sum = 0.f, sum2 = 0.f;
    int j = beg;
    for (; j + 1 < end; j += 2) {
        sum  += g_s[g_csr[j]];
        sum2 += g_s[g_csr[j + 1]];
    }
    if (j < end) sum += g_s[g_csr[j]];
    sum += sum2;
    int deg = end - beg;
    float inv = 1.0f / (float)(deg > 0 ? deg : 1);
    out[i] = sum * inv + b2[0] + g_r[i];
}

// ---------------------------------------------------------------------------
extern "C" void kernel_launch(void* const* d_in, const int* in_sizes, int n_in,
                              void* d_out, int out_size) {
    const float* x   = (const float*)d_in[0];
    const int*   ei  = (const int*)d_in[1];   // int32 OR int64 (warp-detected)
    const float* W1l = (const float*)d_in[2];
    const float* b1  = (const float*)d_in[3];
    const float* W1r = (const float*)d_in[4];
    const float* W2l = (const float*)d_in[5];
    const float* b2  = (const float*)d_in[6];
    const float* W2r = (const float*)d_in[7];
    float* out = (float*)d_out;

    int n = in_sizes[0] / F;      // 100000
    int e = in_sizes[1] / 2;      // 1600000
    int nb = (n + SCAN_CHUNK - 1) / SCAN_CHUNK;   // 98
    int et = (e + 3) / 4;         // edge threads (4 edges each)

    count_kernel<<<(et + 255) / 256, 256>>>(ei, e, n);
    scan_kernel<<<nb, 256>>>(n, nb);
    fill_kernel<<<(et + 255) / 256, 256>>>(ei, e, n);
    agg1_kernel<<<(n * 16 + 255) / 256, 256>>>(x, n);
    h1_kernel<<<((n + 1) / 2 + 127) / 128, 128>>>(x, W1l, b1, W1r, W2l, W2r, n);
    out_kernel<<<(n + 255) / 256, 256>>>(b2, out, n);
}